// round 16
// baseline (speedup 1.0000x reference)
#include <cuda_runtime.h>
#include <cuda_bf16.h>
#include <cstdint>

#define N_NODES 207
#define N_EDGES 1722
#define LDIM    64
#define BATCH   1024
#define N_SLOTS_PAD 208          // 13 passes * 16 warps
#define ADJ_CAP 4096             // >= sum ceil(deg/4)*4 (<= 3444+3*207 = 4065)... see note
#define ADJ_REAL_MAX 4068        // hard bound, ADJ_CAP must exceed
#define PACK_N  4104             // +pad so meta prefetch over-read is safe

// NOTE: sum over nodes of (deg padded to multiple of 4) <= 3444 + 207*3 = 4065.
// ADJ_CAP = 4096 > 4065 only if average pad < 3.15; worst case 4065 < 4096 OK.

// ---------------- device-global CSR scratch (no allocs allowed) ------------
__device__ int g_rowptr4[N_SLOTS_PAD + 1];                   // entry start per SORTED SLOT
__device__ unsigned short g_order[N_SLOTS_PAD];              // slot -> node id (0xFFFF invalid)
__device__ __align__(16) unsigned short g_adj_node[ADJ_CAP]; // nbr*128 (byte offset of bf16 row)
__device__ __align__(16) unsigned short g_adj_edge[ADJ_CAP]; // edge idx; N_EDGES = dummy (w=0)

// ---------------- setup: deterministic pad-4 sorted CSR --------------------
__global__ __launch_bounds__(1024, 1)
void build_csr_kernel(const int* __restrict__ edge_i,
                      const int* __restrict__ edge_j) {
    __shared__ int s_ei[N_EDGES];
    __shared__ int s_ej[N_EDGES];
    __shared__ int s_ng[N_NODES];
    __shared__ int s_off[N_NODES + 1];
    __shared__ unsigned short s_ord[N_SLOTS_PAD];
    __shared__ int s_wcnt[32][208];
    const int tid  = threadIdx.x;
    const int warp = tid >> 5;
    const int lane = tid & 31;

    for (int i = tid; i < N_EDGES; i += 1024) {
        s_ei[i] = edge_i[i];
        s_ej[i] = edge_j[i];
    }
    for (int v = tid; v < N_NODES + 1; v += 1024) s_off[v] = 0;
    for (int i = tid; i < N_SLOTS_PAD; i += 1024) s_ord[i] = 0xFFFFu;
    for (int t = tid; t < ADJ_CAP; t += 1024) {
        g_adj_node[t] = 0;
        g_adj_edge[t] = (unsigned short)N_EDGES;    // dummy -> weight 0
    }
    for (int i = tid; i < 32 * 208; i += 1024) ((int*)s_wcnt)[i] = 0;
    __syncthreads();

    for (int idx = tid; idx < 2 * N_EDGES; idx += 1024) {
        const int e = idx >> 1;
        atomicAdd(&s_off[(idx & 1) ? s_ej[e] : s_ei[e]], 1);
    }
    __syncthreads();

    if (tid < N_NODES) s_ng[tid] = (s_off[tid] + 3) >> 2;
    __syncthreads();

    // parallel rank sort: desc by ng, tie asc id (cross-warp pass balance)
    if (tid < N_NODES) {
        const int nv = s_ng[tid];
        int r = 0;
        for (int u = 0; u < N_NODES; ++u) {
            const int nu = s_ng[u];
            r += (nu > nv) || (nu == nv && u < tid);
        }
        s_ord[r] = (unsigned short)tid;
    }
    __syncthreads();

    // plain pad-4 scan over 208 sorted slots (warp 0, 7 chunks of 32)
    if (warp == 0) {
        int carry = 0;                          // in groups (4 entries)
        #pragma unroll
        for (int c = 0; c < 7; ++c) {
            const int sl = c * 32 + lane;
            const int vn = (sl < N_SLOTS_PAD) ? (int)s_ord[sl] : 0xFFFF;
            const int p  = (vn != 0xFFFF) ? s_ng[vn] : 0;
            int si = p;
            #pragma unroll
            for (int o = 1; o < 32; o <<= 1) {
                const int t = __shfl_up_sync(0xffffffffu, si, o);
                if (lane >= o) si += t;
            }
            const int excl = carry + si - p;
            if (sl < N_SLOTS_PAD) {
                g_rowptr4[sl] = excl * 4;
                if (vn != 0xFFFF) s_off[vn] = excl * 4;
            }
            carry += __shfl_sync(0xffffffffu, si, 31);
        }
        if (lane == 0) g_rowptr4[N_SLOTS_PAD] = carry * 4;
    }
    __syncthreads();
    for (int i = tid; i < N_SLOTS_PAD; i += 1024) g_order[i] = s_ord[i];

    // single-chunk deterministic scatter: 4 sequential rounds per lane
    int myrank[4], myv[4], mynbr[4], mye[4];
    #pragma unroll
    for (int r = 0; r < 4; ++r) {
        const int idx = tid * 4 + r;
        const bool valid = idx < 2 * N_EDGES;
        int v = 207, nbr = 0, e = 0;
        if (valid) {
            e = idx >> 1;
            if (idx & 1) { v = s_ej[e]; nbr = s_ei[e]; }
            else         { v = s_ei[e]; nbr = s_ej[e]; }
        }
        const int prefix = s_wcnt[warp][v];
        const unsigned mask = __match_any_sync(0xffffffffu, v);
        const int rin = __popc(mask & ((1u << lane) - 1u));
        myv[r] = v; mynbr[r] = nbr; mye[r] = e;
        myrank[r] = prefix + rin;
        __syncwarp();
        if (lane == (__ffs(mask) - 1)) s_wcnt[warp][v] = prefix + __popc(mask);
        __syncwarp();
    }
    __syncthreads();

    if (tid < 208) {
        int run = (tid < N_NODES) ? s_off[tid] : 0;
        #pragma unroll
        for (int w2 = 0; w2 < 32; ++w2) {
            const int t = s_wcnt[w2][tid];
            s_wcnt[w2][tid] = run;
            run += t;
        }
    }
    __syncthreads();

    #pragma unroll
    for (int r = 0; r < 4; ++r) {
        const int idx = tid * 4 + r;
        if (idx < 2 * N_EDGES) {
            const int pos = s_wcnt[warp][myv[r]] + myrank[r];
            g_adj_node[pos] = (unsigned short)(mynbr[r] * 128);  // row byte offset
            g_adj_edge[pos] = (unsigned short)mye[r];
        }
    }
}

// ---------------- main kernel: one CTA (512 thr) per batch, occ 4 ----------
// Warp = ONE slot per pass (13 passes); quarter (lane>>3) = entry index in
// group of 4; lane hl (lane&7) covers 8 columns. Per 4-entry group:
// 1 LDS.32 meta (16B-span broadcast, prefetched) + 1 LDS.128 gather (4 rows)
// + PRMT + SHL/FADD + 4 HFMA2. Quarters merge via fp32 shfl butterfly.
#define S_XU_B    0
#define S_W_B     26496
#define S_PACK_B  33408
#define S_ROWP_B  (S_PACK_B + PACK_N * 4)     // 49824
#define S_ORD_B   (S_ROWP_B + 840)            // rowp: 209 ints = 836 -> pad 840
#define SMEM_BYTES (S_ORD_B + 416 + 8)        // ord: 208 u16 = 416

__device__ __forceinline__ __nv_bfloat162 as_bf2(unsigned v) {
    return *reinterpret_cast<__nv_bfloat162*>(&v);
}
__device__ __forceinline__ unsigned as_u32(__nv_bfloat162 v) {
    return *reinterpret_cast<unsigned*>(&v);
}

__global__ __launch_bounds__(512, 4)
void diffusion_gcn_kernel(const float*  __restrict__ inputs,      // (B,2,N,L)
                          const float*  __restrict__ weight_diff, // (S,E)
                          const float*  __restrict__ bias_diff,   // (S,N)
                          const float*  __restrict__ weight_sl,   // (S,N)
                          const int*    __restrict__ ind,         // (B,)
                          float*        __restrict__ out)         // (B,N,L)
{
    extern __shared__ char smem[];
    unsigned*       s_xu   = (unsigned*)(smem + S_XU_B);     // bf16 tile, 32 u32/row
    float*          s_w    = (float*)(smem + S_W_B);         // fp32 slot weights
    unsigned*       s_pack = (unsigned*)(smem + S_PACK_B);   // packed meta
    int*            s_rowp = (int*)(smem + S_ROWP_B);
    unsigned short* s_ord  = (unsigned short*)(smem + S_ORD_B);

    const int b    = blockIdx.x;
    const int tid  = threadIdx.x;
    const int slot = ind[b];
    const float* __restrict__ xg = inputs + (size_t)b * 2 * N_NODES * LDIM;

    // ---- phase A: stage everything (all coalesced) ------------------------
    {   // x -> bf16 tile
        const float4* src = (const float4*)xg;
        uint2* dst = (uint2*)s_xu;
        #pragma unroll 4
        for (int i = tid; i < (N_NODES * LDIM) / 4; i += 512) {
            const float4 v = src[i];
            uint2 p;
            p.x = as_u32(__floats2bfloat162_rn(v.x, v.y));
            p.y = as_u32(__floats2bfloat162_rn(v.z, v.w));
            dst[i] = p;
        }
    }
    {   // slot weight row, zero-padded
        const float* wrow = weight_diff + (size_t)slot * N_EDGES;
        for (int i = tid; i < 1728; i += 512)
            s_w[i] = (i < N_EDGES) ? wrow[i] : 0.0f;
    }
    for (int i = tid; i < N_SLOTS_PAD + 1; i += 512) s_rowp[i] = g_rowptr4[i];
    for (int i = tid; i < N_SLOTS_PAD / 2; i += 512)
        ((unsigned*)s_ord)[i] = ((const unsigned*)g_order)[i];
    __syncthreads();

    // ---- phase B: pack meta from SMEM weights + global CSR (coalesced) ----
    for (int t = tid; t < ADJ_CAP; t += 512) {
        const float w = s_w[(int)g_adj_edge[t]];               // smem gather
        const unsigned wb = (unsigned)__bfloat16_as_ushort(__float2bfloat16(w));
        s_pack[t] = (wb << 16) | (unsigned)g_adj_node[t];      // hi bf16 w | lo byteoff
    }
    if (tid < PACK_N - ADJ_CAP) s_pack[ADJ_CAP + tid] = 0;     // prefetch pad
    __syncthreads();

    // ---- phase C: gather ---------------------------------------------------
    const int warp    = tid >> 5;        // 0..15
    const int lane    = tid & 31;
    const int quarter = lane >> 3;       // entry index within group
    const int hl      = lane & 7;        // 8-column group
    const char* sxb   = (const char*)s_xu + 16 * hl;
    const float* __restrict__ wslrow = weight_sl + (size_t)slot * N_NODES;
    const float* __restrict__ birow  = bias_diff + (size_t)slot * N_NODES;

    #pragma unroll 1
    for (int pass = 0; pass < 13; ++pass) {
        const int sl  = pass * 16 + warp;                  // 13*16 = 208 slots
        const int w   = (int)s_ord[sl];
        const int beg = s_rowp[sl];
        const int ng  = (s_rowp[sl + 1] - beg) >> 2;

        // per-lane meta stream: quarter q reads entry (g*4 + q)
        const unsigned* mp = s_pack + beg + quarter;
        unsigned pk = mp[0];                               // group 0 prefetched

        // diagonal fp32 row prefetch (quarter 0 lanes write the result)
        const float* xr = (w != 0xFFFF) ? (xg + w * LDIM + 8 * hl) : xg;
        const float4 x0 = *(const float4*)xr;

        __nv_bfloat162 c0 = as_bf2(0u), c1 = as_bf2(0u);
        __nv_bfloat162 c2 = as_bf2(0u), c3 = as_bf2(0u);
        float deg = 0.f;

        #pragma unroll 1
        for (int g = 0; g < ng; ++g) {
            const unsigned pn = mp[(g + 1) * 4];           // padded over-read safe
            const uint4 u = *(const uint4*)(sxb + (pk & 0xffffu));
            const __nv_bfloat162 wb = as_bf2(__byte_perm(pk, pk, 0x3232));
            deg += __uint_as_float(pk & 0xffff0000u);
            c0 = __hfma2(wb, as_bf2(u.x), c0);
            c1 = __hfma2(wb, as_bf2(u.y), c1);
            c2 = __hfma2(wb, as_bf2(u.z), c2);
            c3 = __hfma2(wb, as_bf2(u.w), c3);
            pk = pn;
        }

        // unpack to fp32 and butterfly-reduce across quarters (xor 8, 16)
        const unsigned r0 = as_u32(c0), r1 = as_u32(c1);
        const unsigned r2 = as_u32(c2), r3 = as_u32(c3);
        float f0 = __uint_as_float(r0 << 16);
        float f1 = __uint_as_float(r0 & 0xffff0000u);
        float f2 = __uint_as_float(r1 << 16);
        float f3 = __uint_as_float(r1 & 0xffff0000u);
        float f4 = __uint_as_float(r2 << 16);
        float f5 = __uint_as_float(r2 & 0xffff0000u);
        float f6 = __uint_as_float(r3 << 16);
        float f7 = __uint_as_float(r3 & 0xffff0000u);
        #pragma unroll
        for (int o = 8; o <= 16; o <<= 1) {
            f0 += __shfl_xor_sync(0xffffffffu, f0, o);
            f1 += __shfl_xor_sync(0xffffffffu, f1, o);
            f2 += __shfl_xor_sync(0xffffffffu, f2, o);
            f3 += __shfl_xor_sync(0xffffffffu, f3, o);
            f4 += __shfl_xor_sync(0xffffffffu, f4, o);
            f5 += __shfl_xor_sync(0xffffffffu, f5, o);
            f6 += __shfl_xor_sync(0xffffffffu, f6, o);
            f7 += __shfl_xor_sync(0xffffffffu, f7, o);
            deg += __shfl_xor_sync(0xffffffffu, deg, o);
        }

        if (quarter == 0 && w != 0xFFFF) {
            const float4 x1 = *(const float4*)(xr + 4);
            const float sc = deg + 1.0f + __ldg(wslrow + w);
            const float bi = __ldg(birow + w);
            float4 o0, o1;
            o0.x = fmaf(sc, x0.x, bi - f0);
            o0.y = fmaf(sc, x0.y, bi - f1);
            o0.z = fmaf(sc, x0.z, bi - f2);
            o0.w = fmaf(sc, x0.w, bi - f3);
            o1.x = fmaf(sc, x1.x, bi - f4);
            o1.y = fmaf(sc, x1.y, bi - f5);
            o1.z = fmaf(sc, x1.z, bi - f6);
            o1.w = fmaf(sc, x1.w, bi - f7);
            float* op = out + ((size_t)b * N_NODES + w) * LDIM + 8 * hl;
            __stcs((float4*)op, o0);
            __stcs((float4*)(op + 4), o1);
        }
    }
}

// ---------------- launcher ---------------------------------------------
extern "C" void kernel_launch(void* const* d_in, const int* in_sizes, int n_in,
                              void* d_out, int out_size) {
    const float* inputs      = (const float*)d_in[0];
    const float* weight_diff = (const float*)d_in[1];
    const float* bias_diff   = (const float*)d_in[2];
    const float* weight_sl   = (const float*)d_in[3];
    const int*   ind         = (const int*)d_in[4];
    const int*   edge_i      = (const int*)d_in[5];
    const int*   edge_j      = (const int*)d_in[6];
    float*       out         = (float*)d_out;

    static bool attr_set = false;   // host-side config only, not a work guard
    if (!attr_set) {
        cudaFuncSetAttribute(diffusion_gcn_kernel,
                             cudaFuncAttributeMaxDynamicSharedMemorySize,
                             SMEM_BYTES);
        attr_set = true;
    }

    build_csr_kernel<<<1, 1024>>>(edge_i, edge_j);
    diffusion_gcn_kernel<<<BATCH, 512, SMEM_BYTES>>>(
        inputs, weight_diff, bias_diff, weight_sl, ind, out);
}

// round 17
// speedup vs baseline: 1.4458x; 1.4458x over previous
#include <cuda_runtime.h>
#include <cuda_bf16.h>
#include <cstdint>

#define N_NODES 207
#define N_EDGES 1722
#define LDIM    64
#define BATCH   1024
#define N_SLOTS_PAD 224          // 7 passes * 16 warps * 2 slots
#define N_PAIRS 112
#define ADJ_CAP 4608             // >= 4*(sum ng + sum pair diffs) ~ 4144
#define PACK_N  4616             // +8 u32 pad so meta prefetch over-read is safe

// ---------------- device-global CSR scratch (no allocs allowed) ------------
__device__ int g_rowptr4[N_SLOTS_PAD + 1];                   // entry start per SORTED SLOT
__device__ unsigned short g_order[N_SLOTS_PAD];              // slot -> node id (0xFFFF invalid)
__device__ __align__(16) unsigned short g_adj_node[ADJ_CAP]; // nbr*128 (byte offset of bf16 row)
__device__ __align__(16) unsigned short g_adj_edge[ADJ_CAP]; // edge idx; N_EDGES = dummy (w=0)

// ---------------- setup: deterministic pair-padded sorted CSR --------------
__global__ __launch_bounds__(1024, 1)
void build_csr_kernel(const int* __restrict__ edge_i,
                      const int* __restrict__ edge_j) {
    __shared__ int s_ei[N_EDGES];
    __shared__ int s_ej[N_EDGES];
    __shared__ int s_ng[N_NODES];
    __shared__ int s_off[N_NODES + 1];
    __shared__ unsigned short s_ord[N_SLOTS_PAD];
    __shared__ int s_wcnt[32][208];
    const int tid  = threadIdx.x;
    const int warp = tid >> 5;
    const int lane = tid & 31;

    for (int i = tid; i < N_EDGES; i += 1024) {
        s_ei[i] = edge_i[i];
        s_ej[i] = edge_j[i];
    }
    for (int v = tid; v < N_NODES + 1; v += 1024) s_off[v] = 0;
    for (int i = tid; i < N_SLOTS_PAD; i += 1024) s_ord[i] = 0xFFFFu;
    for (int t = tid; t < ADJ_CAP; t += 1024) {
        g_adj_node[t] = 0;
        g_adj_edge[t] = (unsigned short)N_EDGES;    // dummy -> weight 0
    }
    for (int i = tid; i < 32 * 208; i += 1024) ((int*)s_wcnt)[i] = 0;
    __syncthreads();

    for (int idx = tid; idx < 2 * N_EDGES; idx += 1024) {
        const int e = idx >> 1;
        atomicAdd(&s_off[(idx & 1) ? s_ej[e] : s_ei[e]], 1);
    }
    __syncthreads();

    if (tid < N_NODES) s_ng[tid] = (s_off[tid] + 3) >> 2;
    __syncthreads();

    // parallel rank sort: desc by ng, tie asc id (pairs get near-equal ng)
    if (tid < N_NODES) {
        const int nv = s_ng[tid];
        int r = 0;
        for (int u = 0; u < N_NODES; ++u) {
            const int nu = s_ng[u];
            r += (nu > nv) || (nu == nv && u < tid);
        }
        s_ord[r] = (unsigned short)tid;
    }
    __syncthreads();

    // pair scan: 112 pairs, 4 chunks of 32 (warp 0). Pair padded to max ng.
    if (warp == 0) {
        int carry = 0;                          // in pair-max groups
        #pragma unroll
        for (int c = 0; c < 4; ++c) {
            const int q = c * 32 + lane;
            int m = 0, a0 = 0xFFFF, a1 = 0xFFFF;
            if (q < N_PAIRS) {
                a0 = s_ord[2 * q];
                a1 = s_ord[2 * q + 1];
                const int n0 = (a0 != 0xFFFF) ? s_ng[a0] : 0;
                const int n1 = (a1 != 0xFFFF) ? s_ng[a1] : 0;
                m = n0 > n1 ? n0 : n1;
            }
            int si = m;
            #pragma unroll
            for (int o = 1; o < 32; o <<= 1) {
                const int t = __shfl_up_sync(0xffffffffu, si, o);
                if (lane >= o) si += t;
            }
            const int base = (carry + si - m) * 8;      // entries
            if (q < N_PAIRS) {
                g_rowptr4[2 * q]     = base;
                g_rowptr4[2 * q + 1] = base + 4 * m;
                if (a0 != 0xFFFF) s_off[a0] = base;
                if (a1 != 0xFFFF) s_off[a1] = base + 4 * m;
            }
            carry += __shfl_sync(0xffffffffu, si, 31);
        }
        if (lane == 0) g_rowptr4[N_SLOTS_PAD] = carry * 8;
    }
    __syncthreads();
    for (int i = tid; i < N_SLOTS_PAD; i += 1024) g_order[i] = s_ord[i];

    // single-chunk deterministic scatter: 4 sequential rounds per lane
    int myrank[4], myv[4], mynbr[4], mye[4];
    #pragma unroll
    for (int r = 0; r < 4; ++r) {
        const int idx = tid * 4 + r;
        const bool valid = idx < 2 * N_EDGES;
        int v = 207, nbr = 0, e = 0;
        if (valid) {
            e = idx >> 1;
            if (idx & 1) { v = s_ej[e]; nbr = s_ei[e]; }
            else         { v = s_ei[e]; nbr = s_ej[e]; }
        }
        const int prefix = s_wcnt[warp][v];
        const unsigned mask = __match_any_sync(0xffffffffu, v);
        const int rin = __popc(mask & ((1u << lane) - 1u));
        myv[r] = v; mynbr[r] = nbr; mye[r] = e;
        myrank[r] = prefix + rin;
        __syncwarp();
        if (lane == (__ffs(mask) - 1)) s_wcnt[warp][v] = prefix + __popc(mask);
        __syncwarp();
    }
    __syncthreads();

    if (tid < 208) {
        int run = (tid < N_NODES) ? s_off[tid] : 0;
        #pragma unroll
        for (int w2 = 0; w2 < 32; ++w2) {
            const int t = s_wcnt[w2][tid];
            s_wcnt[w2][tid] = run;
            run += t;
        }
    }
    __syncthreads();

    #pragma unroll
    for (int r = 0; r < 4; ++r) {
        const int idx = tid * 4 + r;
        if (idx < 2 * N_EDGES) {
            const int pos = s_wcnt[warp][myv[r]] + myrank[r];
            g_adj_node[pos] = (unsigned short)(mynbr[r] * 128);  // row byte offset
            g_adj_edge[pos] = (unsigned short)mye[r];
        }
    }
}

// ---------------- main kernel: one CTA (512 thr) per batch, occ 4 ----------
// Staging warp-specialized: warps 0-9 stage the bf16 x tile; warps 10-15
// load tables+weights then pack meta (named barrier 1, 192 thr); one
// __syncthreads total. Gather: warp = 2 sorted slots (halves, equal padded
// ng); lane covers 4 columns via uint2. Per 4-entry group per half:
// broadcast LDS.128 meta (prefetched) + 4 x (LDS.64 + PRMT + FADD + 2 HFMA2).
#define S_XU_B    0
#define S_W_B     26496
#define S_PACK_B  33408
#define S_ROWP_B  (S_PACK_B + PACK_N * 4)     // 51872
#define S_ORD_B   (S_ROWP_B + 904)            // rowp 225 ints
#define SMEM_BYTES (S_ORD_B + 448 + 8)        // ord 224 u16

__device__ __forceinline__ __nv_bfloat162 as_bf2(unsigned v) {
    return *reinterpret_cast<__nv_bfloat162*>(&v);
}
__device__ __forceinline__ unsigned as_u32(__nv_bfloat162 v) {
    return *reinterpret_cast<unsigned*>(&v);
}

#define ENTRY(PK) do {                                                \
    const uint2 u = *(const uint2*)(sxb + ((PK) & 0xffffu));          \
    const __nv_bfloat162 wb = as_bf2(__byte_perm((PK), (PK), 0x3232));\
    deg += __uint_as_float((PK) & 0xffff0000u);                       \
    c0 = __hfma2(wb, as_bf2(u.x), c0);                                \
    c1 = __hfma2(wb, as_bf2(u.y), c1);                                \
} while (0)

__global__ __launch_bounds__(512, 4)
void diffusion_gcn_kernel(const float*  __restrict__ inputs,      // (B,2,N,L)
                          const float*  __restrict__ weight_diff, // (S,E)
                          const float*  __restrict__ bias_diff,   // (S,N)
                          const float*  __restrict__ weight_sl,   // (S,N)
                          const int*    __restrict__ ind,         // (B,)
                          float*        __restrict__ out)         // (B,N,L)
{
    extern __shared__ char smem[];
    unsigned*       s_xu   = (unsigned*)(smem + S_XU_B);     // bf16 tile, 32 u32/row
    float*          s_w    = (float*)(smem + S_W_B);         // fp32 slot weights
    unsigned*       s_pack = (unsigned*)(smem + S_PACK_B);   // packed meta
    int*            s_rowp = (int*)(smem + S_ROWP_B);
    unsigned short* s_ord  = (unsigned short*)(smem + S_ORD_B);

    const int b    = blockIdx.x;
    const int tid  = threadIdx.x;
    const int slot = ind[b];
    const float* __restrict__ xg = inputs + (size_t)b * 2 * N_NODES * LDIM;

    // ---- staging: warp-specialized, overlapped ----------------------------
    if (tid < 320) {
        // warps 0-9: x -> bf16 tile (coalesced)
        const float4* src = (const float4*)xg;
        uint2* dst = (uint2*)s_xu;
        #pragma unroll 4
        for (int i = tid; i < (N_NODES * LDIM) / 4; i += 320) {
            const float4 v = src[i];
            uint2 p;
            p.x = as_u32(__floats2bfloat162_rn(v.x, v.y));
            p.y = as_u32(__floats2bfloat162_rn(v.z, v.w));
            dst[i] = p;
        }
    } else {
        // warps 10-15 (192 thr): tables + weights, then pack meta
        const int t2 = tid - 320;
        for (int i = t2; i < N_SLOTS_PAD + 1; i += 192) s_rowp[i] = g_rowptr4[i];
        for (int i = t2; i < N_SLOTS_PAD / 2; i += 192)
            ((unsigned*)s_ord)[i] = ((const unsigned*)g_order)[i];
        const float* wrow = weight_diff + (size_t)slot * N_EDGES;
        for (int i = t2; i < 1728; i += 192)
            s_w[i] = (i < N_EDGES) ? wrow[i] : 0.0f;
        asm volatile("bar.sync 1, 192;" ::: "memory");     // sub-group barrier
        for (int t = t2; t < ADJ_CAP; t += 192) {
            const float w = s_w[(int)g_adj_edge[t]];        // smem gather
            const unsigned wb = (unsigned)__bfloat16_as_ushort(__float2bfloat16(w));
            s_pack[t] = (wb << 16) | (unsigned)g_adj_node[t];
        }
        if (t2 < PACK_N - ADJ_CAP) s_pack[ADJ_CAP + t2] = 0;  // prefetch pad
    }
    __syncthreads();

    // ---- gather -------------------------------------------------------------
    const int warp = tid >> 5;           // 0..15
    const int lane = tid & 31;
    const int half = lane >> 4;          // slot within pair
    const int hl   = lane & 15;          // 4-column group within slot
    const char* sxb = (const char*)s_xu + 8 * hl;
    const float* __restrict__ wslrow = weight_sl + (size_t)slot * N_NODES;
    const float* __restrict__ birow  = bias_diff + (size_t)slot * N_NODES;

    #pragma unroll 1
    for (int pass = 0; pass < 7; ++pass) {
        const int sl  = pass * 32 + warp * 2 + half;       // 7*32 = 224 slots
        const int w   = (int)s_ord[sl];
        const int beg = s_rowp[sl];
        const int ng  = (s_rowp[sl + 1] - beg) >> 2;       // uniform across pair

        const uint4* mp = (const uint4*)(s_pack + beg);
        uint4 p = mp[0];                                    // group 0 prefetched

        // prefetch diagonal fp32 columns (global, L2-hot)
        const float* xr = (w != 0xFFFF) ? (xg + w * LDIM + 4 * hl) : xg;
        const float4 x0 = *(const float4*)xr;

        __nv_bfloat162 c0 = as_bf2(0u), c1 = as_bf2(0u);
        float deg = 0.f;

        #pragma unroll 1
        for (int g = 0; g < ng; ++g) {
            const uint4 pn = mp[g + 1];                     // padded over-read safe
            ENTRY(p.x);
            ENTRY(p.y);
            ENTRY(p.z);
            ENTRY(p.w);
            p = pn;
        }

        if (w != 0xFFFF) {
            const float sc = deg + 1.0f + __ldg(wslrow + w);
            const float bi = __ldg(birow + w);
            const unsigned r0 = as_u32(c0), r1 = as_u32(c1);
            float4 o;
            o.x = fmaf(sc, x0.x, bi - __uint_as_float(r0 << 16));
            o.y = fmaf(sc, x0.y, bi - __uint_as_float(r0 & 0xffff0000u));
            o.z = fmaf(sc, x0.z, bi - __uint_as_float(r1 << 16));
            o.w = fmaf(sc, x0.w, bi - __uint_as_float(r1 & 0xffff0000u));
            float* op = out + ((size_t)b * N_NODES + w) * LDIM + 4 * hl;
            __stcs((float4*)op, o);                         // streaming store
        }
    }
}

// ---------------- launcher ---------------------------------------------
extern "C" void kernel_launch(void* const* d_in, const int* in_sizes, int n_in,
                              void* d_out, int out_size) {
    const float* inputs      = (const float*)d_in[0];
    const float* weight_diff = (const float*)d_in[1];
    const float* bias_diff   = (const float*)d_in[2];
    const float* weight_sl   = (const float*)d_in[3];
    const int*   ind         = (const int*)d_in[4];
    const int*   edge_i      = (const int*)d_in[5];
    const int*   edge_j      = (const int*)d_in[6];
    float*       out         = (float*)d_out;

    static bool attr_set = false;   // host-side config only, not a work guard
    if (!attr_set) {
        cudaFuncSetAttribute(diffusion_gcn_kernel,
                             cudaFuncAttributeMaxDynamicSharedMemorySize,
                             SMEM_BYTES);
        attr_set = true;
    }

    build_csr_kernel<<<1, 1024>>>(edge_i, edge_j);
    diffusion_gcn_kernel<<<BATCH, 512, SMEM_BYTES>>>(
        inputs, weight_diff, bias_diff, weight_sl, ind, out);
}